// round 1
// baseline (speedup 1.0000x reference)
#include <cuda_runtime.h>
#include <cuda_bf16.h>

#define N_NODES 50000
#define N_EDGES 800000
#define IN_F    512
#define OUT_F   96
#define ALPHA   0.1f
#define ITERS   10

// ---------------- device scratch (no allocations allowed) ----------------
__device__ float g_support[N_NODES * OUT_F];   // prev (= x@W), kept for residual
__device__ float g_bufA[N_NODES * OUT_F];      // ping-pong buffer
__device__ int   g_counts[N_NODES];
__device__ int   g_rowptr[N_NODES + 1];
__device__ int   g_offsets[N_NODES];
__device__ int   g_col[N_EDGES];
__device__ float g_val[N_EDGES];

// ---------------- CSR build ----------------
__global__ void zero_counts_kernel() {
    int i = blockIdx.x * blockDim.x + threadIdx.x;
    if (i < N_NODES) g_counts[i] = 0;
}

__global__ void hist_kernel(const int* __restrict__ dst) {
    int e = blockIdx.x * blockDim.x + threadIdx.x;
    if (e < N_EDGES) atomicAdd(&g_counts[dst[e]], 1);
}

// single-block exclusive scan over g_counts -> g_rowptr / g_offsets
__global__ void scan_kernel() {
    __shared__ int sh[1024];
    __shared__ int carry_sh;
    int tid = threadIdx.x;
    if (tid == 0) carry_sh = 0;
    __syncthreads();
    for (int base = 0; base < N_NODES; base += 1024) {
        int i = base + tid;
        int v = (i < N_NODES) ? g_counts[i] : 0;
        sh[tid] = v;
        __syncthreads();
        // Hillis-Steele inclusive scan
        #pragma unroll
        for (int off = 1; off < 1024; off <<= 1) {
            int t = (tid >= off) ? sh[tid - off] : 0;
            __syncthreads();
            sh[tid] += t;
            __syncthreads();
        }
        int c = carry_sh;
        int incl = sh[tid] + c;
        int excl = incl - v;
        if (i < N_NODES) { g_rowptr[i] = excl; g_offsets[i] = excl; }
        __syncthreads();
        if (tid == 0) carry_sh = c + sh[1023];
        __syncthreads();
    }
    if (tid == 0) g_rowptr[N_NODES] = carry_sh;
}

__global__ void scatter_kernel(const int* __restrict__ src,
                               const int* __restrict__ dst,
                               const float* __restrict__ val) {
    int e = blockIdx.x * blockDim.x + threadIdx.x;
    if (e < N_EDGES) {
        int d = dst[e];
        int pos = atomicAdd(&g_offsets[d], 1);
        g_col[pos] = src[e];
        g_val[pos] = val[e] * (1.0f - ALPHA);  // fold (1-alpha) into edge value
    }
}

// ---------------- GEMM: g_support = x @ W  (N_NODES x IN_F x OUT_F) -------
#define GT_M  128
#define GT_KT 16
#define GPAD  132   // TM + 4 padding (keeps float4 alignment, limits conflicts)

__global__ __launch_bounds__(256) void gemm_kernel(const float* __restrict__ x,
                                                   const float* __restrict__ w) {
    __shared__ float xs[GT_KT][GPAD];    // transposed x tile [k][row]
    __shared__ float ws[GT_KT][OUT_F];   // W tile [k][col]

    int tid = threadIdx.x;
    int row0 = blockIdx.x * GT_M;
    int i = tid & 31;          // row group (4 rows)
    int j = tid >> 5;          // col group (12 cols)
    int r0 = i * 4;
    int c0 = j * 12;

    float acc[4][12];
    #pragma unroll
    for (int a = 0; a < 4; a++)
        #pragma unroll
        for (int b = 0; b < 12; b++) acc[a][b] = 0.0f;

    for (int k0 = 0; k0 < IN_F; k0 += GT_KT) {
        // load x tile (128 rows x 16 k) transposed into xs[k][row]
        for (int idx = tid; idx < GT_M * GT_KT; idx += 256) {
            int k = idx & (GT_KT - 1);
            int r = idx >> 4;
            int gr = row0 + r;
            float v = (gr < N_NODES) ? x[(long)gr * IN_F + k0 + k] : 0.0f;
            xs[k][r] = v;
        }
        // load W tile (16 k x 96 cols)
        for (int idx = tid; idx < GT_KT * OUT_F; idx += 256) {
            int k = idx / OUT_F;
            int c = idx - k * OUT_F;
            ws[k][c] = w[(long)(k0 + k) * OUT_F + c];
        }
        __syncthreads();

        #pragma unroll
        for (int k = 0; k < GT_KT; k++) {
            float4 xv = *reinterpret_cast<const float4*>(&xs[k][r0]);
            float wv[12];
            #pragma unroll
            for (int q = 0; q < 3; q++) {
                float4 t = *reinterpret_cast<const float4*>(&ws[k][c0 + q * 4]);
                wv[q * 4 + 0] = t.x; wv[q * 4 + 1] = t.y;
                wv[q * 4 + 2] = t.z; wv[q * 4 + 3] = t.w;
            }
            float xr[4] = {xv.x, xv.y, xv.z, xv.w};
            #pragma unroll
            for (int a = 0; a < 4; a++)
                #pragma unroll
                for (int b = 0; b < 12; b++)
                    acc[a][b] = fmaf(xr[a], wv[b], acc[a][b]);
        }
        __syncthreads();
    }

    #pragma unroll
    for (int a = 0; a < 4; a++) {
        int gr = row0 + r0 + a;
        if (gr < N_NODES) {
            #pragma unroll
            for (int b = 0; b < 12; b++)
                g_support[(long)gr * OUT_F + c0 + b] = acc[a][b];
        }
    }
}

// ---------------- SPMM + residual + relu ----------------
// in_sel/out_sel: 0 = g_support, 1 = g_bufA, 2 = d_out
__global__ __launch_bounds__(256) void spmm_kernel(float* __restrict__ dout,
                                                   int in_sel, int out_sel) {
    const float* h = (in_sel == 0) ? g_support : (in_sel == 1) ? g_bufA : dout;
    float* out = (out_sel == 1) ? g_bufA : dout;

    int warp = (blockIdx.x * blockDim.x + threadIdx.x) >> 5;
    int lane = threadIdx.x & 31;
    if (warp >= N_NODES) return;

    int beg = g_rowptr[warp];
    int end = g_rowptr[warp + 1];

    float a0 = 0.0f, a1 = 0.0f, a2 = 0.0f;
    #pragma unroll 2
    for (int e = beg; e < end; e++) {
        int s = g_col[e];
        float v = g_val[e];               // already scaled by (1-alpha)
        const float* hp = h + (long)s * OUT_F;
        a0 = fmaf(v, hp[lane],      a0);
        a1 = fmaf(v, hp[lane + 32], a1);
        a2 = fmaf(v, hp[lane + 64], a2);
    }

    long o = (long)warp * OUT_F + lane;
    out[o]      = fmaxf(a0 + ALPHA * g_support[o],      0.0f);
    out[o + 32] = fmaxf(a1 + ALPHA * g_support[o + 32], 0.0f);
    out[o + 64] = fmaxf(a2 + ALPHA * g_support[o + 64], 0.0f);
}

// ---------------- launch ----------------
extern "C" void kernel_launch(void* const* d_in, const int* in_sizes, int n_in,
                              void* d_out, int out_size) {
    const float* x  = (const float*)d_in[0];
    const float* w  = (const float*)d_in[1];
    const int* esrc = (const int*)d_in[2];
    const int* edst = (const int*)d_in[3];
    const float* ev = (const float*)d_in[4];
    float* dout = (float*)d_out;

    // CSR build
    zero_counts_kernel<<<(N_NODES + 255) / 256, 256>>>();
    hist_kernel<<<(N_EDGES + 255) / 256, 256>>>(edst);
    scan_kernel<<<1, 1024>>>();
    scatter_kernel<<<(N_EDGES + 255) / 256, 256>>>(esrc, edst, ev);

    // support = x @ W
    gemm_kernel<<<(N_NODES + GT_M - 1) / GT_M, 256>>>(x, w);

    // 10 propagation iterations; iter 10 (even) lands in d_out
    int spmm_blocks = (N_NODES * 32 + 255) / 256;
    for (int it = 1; it <= ITERS; it++) {
        int in_sel  = (it == 1) ? 0 : ((it & 1) == 0 ? 1 : 2);
        int out_sel = ((it & 1) == 1) ? 1 : 2;
        spmm_kernel<<<spmm_blocks, 256>>>(dout, in_sel, out_sel);
    }
}

// round 3
// speedup vs baseline: 1.5776x; 1.5776x over previous
#include <cuda_runtime.h>
#include <cuda_bf16.h>
#include <cstdint>

#define N_NODES 50000
#define N_EDGES 800000
#define IN_F    512
#define OUT_F   96
#define ALPHA   0.1f
#define ITERS   10

// ---------------- device scratch ----------------
__device__ float g_support[N_NODES * OUT_F];
__device__ float g_bufA[N_NODES * OUT_F];
__device__ int   g_counts[N_NODES];
__device__ int   g_rowptr[N_NODES + 1];
__device__ int   g_offsets[N_NODES];
__device__ int   g_col[N_EDGES];
__device__ float g_val[N_EDGES];
__device__ int   g_bsum[64];
__device__ int   g_boff[64];

__device__ __forceinline__ uint32_t smem_u32(const void* p) {
    uint32_t a;
    asm("{ .reg .u64 t; cvta.to.shared.u64 t, %1; cvt.u32.u64 %0, t; }" : "=r"(a) : "l"(p));
    return a;
}

// ---------------- CSR build ----------------
__global__ void zero_counts_kernel() {
    int i = blockIdx.x * blockDim.x + threadIdx.x;
    if (i < N_NODES) g_counts[i] = 0;
}
__global__ void hist_kernel(const int* __restrict__ dst) {
    int e = blockIdx.x * blockDim.x + threadIdx.x;
    if (e < N_EDGES) atomicAdd(&g_counts[dst[e]], 1);
}

#define SCAN_B 1024
#define N_SCAN_BLOCKS ((N_NODES + SCAN_B - 1) / SCAN_B)   // 49

__global__ void scan_block_kernel() {
    __shared__ int sh[SCAN_B];
    int tid = threadIdx.x;
    int i = blockIdx.x * SCAN_B + tid;
    int v = (i < N_NODES) ? g_counts[i] : 0;
    sh[tid] = v;
    __syncthreads();
    #pragma unroll
    for (int off = 1; off < SCAN_B; off <<= 1) {
        int t = (tid >= off) ? sh[tid - off] : 0;
        __syncthreads();
        sh[tid] += t;
        __syncthreads();
    }
    if (i < N_NODES) g_rowptr[i] = sh[tid] - v;     // block-local exclusive
    if (tid == SCAN_B - 1) g_bsum[blockIdx.x] = sh[tid];
}

__global__ void scan_bsum_kernel() {
    __shared__ int sh[64];
    int tid = threadIdx.x;
    int v = (tid < N_SCAN_BLOCKS) ? g_bsum[tid] : 0;
    sh[tid] = v;
    __syncthreads();
    #pragma unroll
    for (int off = 1; off < 64; off <<= 1) {
        int t = (tid >= off) ? sh[tid - off] : 0;
        __syncthreads();
        sh[tid] += t;
        __syncthreads();
    }
    if (tid < N_SCAN_BLOCKS) g_boff[tid] = sh[tid] - v;
    if (tid == 63) g_rowptr[N_NODES] = sh[63];
}

__global__ void scan_add_kernel() {
    int i = blockIdx.x * blockDim.x + threadIdx.x;
    if (i < N_NODES) {
        int v = g_rowptr[i] + g_boff[i >> 10];
        g_rowptr[i] = v;
        g_offsets[i] = v;
    }
}

__global__ void scatter_kernel(const int* __restrict__ src,
                               const int* __restrict__ dst,
                               const float* __restrict__ val) {
    int e = blockIdx.x * blockDim.x + threadIdx.x;
    if (e < N_EDGES) {
        int d = dst[e];
        int pos = atomicAdd(&g_offsets[d], 1);
        g_col[pos] = src[e];
        g_val[pos] = val[e] * (1.0f - ALPHA);
    }
}

// ---------------- HMMA GEMM: g_support = x @ W ----------------
// 3-term bf16 split: D = xh@Wh + xh@Wl + xl@Wh  (fp32 accumulate)
// mma.sync.m16n8k16 row.col  — valid on base sm_103 target (no tcgen05).
// CTA: 128 rows x 96 cols, 8 warps, each warp 16 rows x 96 cols.
#define BM 128
#define BK 32
#define APAD 40   // bf16 elems per padded row (32 + 8) -> conflict-free ldmatrix

__device__ __forceinline__ void ldmat4(uint32_t* r, uint32_t addr) {
    asm volatile("ldmatrix.sync.aligned.m8n8.x4.shared.b16 {%0,%1,%2,%3}, [%4];"
                 : "=r"(r[0]), "=r"(r[1]), "=r"(r[2]), "=r"(r[3]) : "r"(addr));
}
__device__ __forceinline__ void mma16816(float* c, const uint32_t* a,
                                         uint32_t b0, uint32_t b1) {
    asm volatile("mma.sync.aligned.m16n8k16.row.col.f32.bf16.bf16.f32 "
                 "{%0,%1,%2,%3}, {%4,%5,%6,%7}, {%8,%9}, {%0,%1,%2,%3};"
                 : "+f"(c[0]), "+f"(c[1]), "+f"(c[2]), "+f"(c[3])
                 : "r"(a[0]), "r"(a[1]), "r"(a[2]), "r"(a[3]), "r"(b0), "r"(b1));
}

__global__ __launch_bounds__(256) void gemm_mma_kernel(const float* __restrict__ x,
                                                       const float* __restrict__ w) {
    __shared__ __nv_bfloat16 Ahi[BM * APAD];
    __shared__ __nv_bfloat16 Alo[BM * APAD];
    __shared__ __nv_bfloat16 Bhi[OUT_F * APAD];   // n-major: Bhi[n*APAD + k]
    __shared__ __nv_bfloat16 Blo[OUT_F * APAD];

    int tid = threadIdx.x;
    int wid = tid >> 5;
    int lane = tid & 31;
    int row0 = blockIdx.x * BM;

    float acc[12][4];
    #pragma unroll
    for (int j = 0; j < 12; j++)
        #pragma unroll
        for (int q = 0; q < 4; q++) acc[j][q] = 0.0f;

    uint32_t ahi_base = smem_u32(Ahi);
    uint32_t alo_base = smem_u32(Alo);

    // ldmatrix per-lane address components (x4: m0 rows 0-7, m1 rows 8-15,
    // m2 rows 0-7 k+8, m3 rows 8-15 k+8 -> matches a0..a3 fragment layout)
    int lm_row = wid * 16 + (lane & 7) + ((lane >> 3) & 1) * 8;
    int lm_k8  = (lane >> 4) * 8;

    // B fragment addressing (n-major): n = j*8 + lane/4, k = ks*16 + (lane%4)*2
    int bn = lane >> 2;
    int bk = (lane & 3) * 2;

    for (int c = 0; c < IN_F / BK; c++) {
        int k0g = c * BK;

        // ---- load + split A tile: 128 rows x 32 k ----
        {
            int r = tid >> 1;
            int kh = (tid & 1) * 16;
            int gr = row0 + r;
            const float4* src = reinterpret_cast<const float4*>(
                &x[(long)gr * IN_F + k0g + kh]);
            #pragma unroll
            for (int q = 0; q < 4; q++) {
                float4 v = (gr < N_NODES) ? src[q]
                                          : make_float4(0.f, 0.f, 0.f, 0.f);
                float vv[4] = {v.x, v.y, v.z, v.w};
                __nv_bfloat162 th2[2], tl2[2];
                #pragma unroll
                for (int p = 0; p < 4; p++) {
                    __nv_bfloat16 h = __float2bfloat16(vv[p]);
                    __nv_bfloat16 l = __float2bfloat16(vv[p] - __bfloat162float(h));
                    if (p & 1) { th2[p >> 1].y = h; tl2[p >> 1].y = l; }
                    else       { th2[p >> 1].x = h; tl2[p >> 1].x = l; }
                }
                int o = r * APAD + kh + q * 4;
                *reinterpret_cast<__nv_bfloat162*>(&Ahi[o])     = th2[0];
                *reinterpret_cast<__nv_bfloat162*>(&Ahi[o + 2]) = th2[1];
                *reinterpret_cast<__nv_bfloat162*>(&Alo[o])     = tl2[0];
                *reinterpret_cast<__nv_bfloat162*>(&Alo[o + 2]) = tl2[1];
            }
        }

        // ---- load + split + transpose W tile: 32 k x 96 n -> [n][k] ----
        #pragma unroll
        for (int j = 0; j < 12; j++) {
            int idx = j * 256 + tid;          // 0..3071
            int k = idx / OUT_F;
            int n = idx - k * OUT_F;
            float v = w[(long)(k0g + k) * OUT_F + n];
            __nv_bfloat16 h = __float2bfloat16(v);
            __nv_bfloat16 l = __float2bfloat16(v - __bfloat162float(h));
            Bhi[n * APAD + k] = h;
            Blo[n * APAD + k] = l;
        }
        __syncthreads();

        #pragma unroll
        for (int ks = 0; ks < 2; ks++) {
            uint32_t a_off = (uint32_t)(lm_row * APAD + ks * 16 + lm_k8) * 2;
            uint32_t ah[4], al[4];
            ldmat4(ah, ahi_base + a_off);
            ldmat4(al, alo_base + a_off);
            int kk = ks * 16 + bk;
            #pragma unroll
            for (int j = 0; j < 12; j++) {
                int n = j * 8 + bn;
                uint32_t bh0 = *reinterpret_cast<const uint32_t*>(&Bhi[n * APAD + kk]);
                uint32_t bh1 = *reinterpret_cast<const uint32_t*>(&Bhi[n * APAD + kk + 8]);
                uint32_t bl0 = *reinterpret_cast<const uint32_t*>(&Blo[n * APAD + kk]);
                uint32_t bl1 = *reinterpret_cast<const uint32_t*>(&Blo[n * APAD + kk + 8]);
                mma16816(acc[j], ah, bh0, bh1);
                mma16816(acc[j], ah, bl0, bl1);
                mma16816(acc[j], al, bh0, bh1);
            }
        }
        __syncthreads();
    }

    // ---- epilogue ----
    int r0 = row0 + wid * 16 + (lane >> 2);
    int cb = (lane & 3) * 2;
    #pragma unroll
    for (int j = 0; j < 12; j++) {
        int cc = j * 8 + cb;
        if (r0 < N_NODES) {
            float2 t = make_float2(acc[j][0], acc[j][1]);
            *reinterpret_cast<float2*>(&g_support[(long)r0 * OUT_F + cc]) = t;
        }
        if (r0 + 8 < N_NODES) {
            float2 t = make_float2(acc[j][2], acc[j][3]);
            *reinterpret_cast<float2*>(&g_support[(long)(r0 + 8) * OUT_F + cc]) = t;
        }
    }
}

// ---------------- SPMM + residual + relu ----------------
__global__ __launch_bounds__(256) void spmm_kernel(float* __restrict__ dout,
                                                   int in_sel, int out_sel) {
    const float* __restrict__ h = (in_sel == 0) ? g_support : (in_sel == 1) ? g_bufA : dout;
    float* __restrict__ out = (out_sel == 1) ? g_bufA : dout;

    int warp = (blockIdx.x * blockDim.x + threadIdx.x) >> 5;
    int lane = threadIdx.x & 31;
    if (warp >= N_NODES) return;

    int beg = g_rowptr[warp];
    int end = g_rowptr[warp + 1];

    float a0 = 0.0f, a1 = 0.0f, a2 = 0.0f;
    int e = beg;
    for (; e + 2 <= end; e += 2) {
        int s0 = __ldg(&g_col[e]);
        int s1 = __ldg(&g_col[e + 1]);
        float v0 = __ldg(&g_val[e]);
        float v1 = __ldg(&g_val[e + 1]);
        const float* p0 = h + (long)s0 * OUT_F;
        const float* p1 = h + (long)s1 * OUT_F;
        float x00 = p0[lane], x01 = p0[lane + 32], x02 = p0[lane + 64];
        float x10 = p1[lane], x11 = p1[lane + 32], x12 = p1[lane + 64];
        a0 = fmaf(v0, x00, a0); a1 = fmaf(v0, x01, a1); a2 = fmaf(v0, x02, a2);
        a0 = fmaf(v1, x10, a0); a1 = fmaf(v1, x11, a1); a2 = fmaf(v1, x12, a2);
    }
    if (e < end) {
        int s = __ldg(&g_col[e]);
        float v = __ldg(&g_val[e]);
        const float* p = h + (long)s * OUT_F;
        a0 = fmaf(v, p[lane], a0);
        a1 = fmaf(v, p[lane + 32], a1);
        a2 = fmaf(v, p[lane + 64], a2);
    }

    long o = (long)warp * OUT_F + lane;
    out[o]      = fmaxf(fmaf(ALPHA, g_support[o],      a0), 0.0f);
    out[o + 32] = fmaxf(fmaf(ALPHA, g_support[o + 32], a1), 0.0f);
    out[o + 64] = fmaxf(fmaf(ALPHA, g_support[o + 64], a2), 0.0f);
}

// ---------------- launch ----------------
extern "C" void kernel_launch(void* const* d_in, const int* in_sizes, int n_in,
                              void* d_out, int out_size) {
    const float* x  = (const float*)d_in[0];
    const float* w  = (const float*)d_in[1];
    const int* esrc = (const int*)d_in[2];
    const int* edst = (const int*)d_in[3];
    const float* ev = (const float*)d_in[4];
    float* dout = (float*)d_out;

    // CSR build
    zero_counts_kernel<<<(N_NODES + 255) / 256, 256>>>();
    hist_kernel<<<(N_EDGES + 255) / 256, 256>>>(edst);
    scan_block_kernel<<<N_SCAN_BLOCKS, SCAN_B>>>();
    scan_bsum_kernel<<<1, 64>>>();
    scan_add_kernel<<<(N_NODES + 255) / 256, 256>>>();
    scatter_kernel<<<(N_EDGES + 255) / 256, 256>>>(esrc, edst, ev);

    // support = x @ W  (HMMA, 3-term bf16 split)
    gemm_mma_kernel<<<(N_NODES + BM - 1) / BM, 256>>>(x, w);

    // 10 propagation iterations; iteration 10 lands in d_out
    int spmm_blocks = (N_NODES * 32 + 255) / 256;
    for (int it = 1; it <= ITERS; it++) {
        int in_sel  = (it == 1) ? 0 : ((it & 1) == 0 ? 1 : 2);
        int out_sel = ((it & 1) == 1) ? 1 : 2;
        spmm_kernel<<<spmm_blocks, 256>>>(dout, in_sel, out_sel);
    }
}